// round 10
// baseline (speedup 1.0000x reference)
#include <cuda_runtime.h>
#include <cuda_bf16.h>

// Problem constants
#define NSPL 191               // 3*64 - 1 spline dims
#define KB   64                // bins

__device__ __forceinline__ float softplus_f(float x) {
    return fmaxf(x, 0.0f) + __logf(1.0f + __expf(-fabsf(x)));
}

__device__ __forceinline__ float sel4f(const float a[4], int k) {
    float x01 = (k & 1) ? a[1] : a[0];
    float x23 = (k & 1) ? a[3] : a[2];
    return (k & 2) ? x23 : x01;
}
__device__ __forceinline__ int sel4i(const int a[4], int k) {
    int x01 = (k & 1) ? a[1] : a[0];
    int x23 = (k & 1) ? a[3] : a[2];
    return (k & 2) ? x23 : x01;
}

// Hybrid: per warp, 4 cuts. Load+scan phase runs warp-wide per cut (serial
// over 4 cuts; every stream LDG covers 128 contiguous bytes of ONE row ->
// 1-2 L1 wavefronts). Tail phase runs the 4 cuts in parallel in lane groups.
__global__ __launch_bounds__(256)
void rqs_logdet4h_kernel(const float* __restrict__ value,
                         const float* __restrict__ delta_spline,
                         const int*   __restrict__ genes_oi,
                         const int*   __restrict__ local_gene_ix,
                         const float* __restrict__ spline_weight,
                         float*       __restrict__ out,
                         int n)
{
    const unsigned FULL = 0xffffffffu;
    const float WINDOW_A      = -10000.0f;
    const float INV_AB        = 1.0f / 20000.0f;
    const float MBW           = 0.001f;
    const float MBH           = 0.001f;
    const float MDER          = 0.001f;
    const float DEFAULT_INIT  = 0.53974366f;                 // log(exp(0.999)-1)
    const float OUT_CONST     = -0.69314718f - 9.90348755f;  // LOG_HALF - LOG_AB
    const float cH            = 1.0f - MBH * KB;             // 0.936
    const float cW            = 1.0f - MBW * KB;

    const int lane = threadIdx.x & 31;
    int warp = (int)((blockIdx.x * (unsigned)blockDim.x + threadIdx.x) >> 5);
    long long cb = (long long)warp * 4;
    if (cb >= n) return;                         // warp-uniform exit

    // ---- prologue: lanes 0..3 fetch per-cut gene + value, broadcast ----
    int   gene_l = 0;
    float val_l  = 0.0f;
    {
        long long ccl = cb + lane;
        int cc = (ccl < n) ? (int)ccl : (n - 1);
        if (lane < 4) {
            gene_l = genes_oi[local_gene_ix[cc]];
            val_l  = value[cc];
        }
    }

    // per-cut state captured during the serial phase (broadcast in all lanes)
    int   idxr[4];
    float c0r[4], ehr[4], ewr[4], swr_[4], ishr[4];

    #pragma unroll
    for (int r = 0; r < 4; ++r) {
        long long ccl = cb + r;
        int cc = (ccl < n) ? (int)ccl : (n - 1);
        const float* ds = delta_spline + (long long)cc * NSPL;
        int gene = __shfl_sync(FULL, gene_l, r);
        const float* sw = spline_weight + (long long)gene * NSPL;

        // warp-wide contiguous loads: lane l gets bins l and 32+l
        float uw0 = ds[lane]          + sw[lane];
        float uw1 = ds[32 + lane]     + sw[32 + lane];
        float uh0 = ds[KB + lane]     + sw[KB + lane];
        float uh1 = ds[KB + 32 + lane]+ sw[KB + 32 + lane];

        float ew0 = __expf(uw0), ew1 = __expf(uw1);
        float eh0 = __expf(uh0), eh1 = __expf(uh1);

        // widths total: butterfly
        float Sw = ew0 + ew1;
        #pragma unroll
        for (int o = 16; o; o >>= 1) Sw += __shfl_xor_sync(FULL, Sw, o);

        // heights cumsum: two KS scans + carry
        float s0 = eh0;
        #pragma unroll
        for (int o = 1; o < 32; o <<= 1) {
            float u = __shfl_up_sync(FULL, s0, o);
            if (lane >= o) s0 += u;
        }
        float T0 = __shfl_sync(FULL, s0, 31);
        float s1 = eh1;
        #pragma unroll
        for (int o = 1; o < 32; o <<= 1) {
            float u = __shfl_up_sync(FULL, s1, o);
            if (lane >= o) s1 += u;
        }
        float cum_lo = s0;                 // inclusive cumexp at bin l
        float cum_hi = T0 + s1;            // inclusive cumexp at bin 32+l
        float Sh = T0 + __shfl_sync(FULL, s1, 31);

        // x for this cut (broadcast from prologue)
        float v  = __shfl_sync(FULL, val_l, r);
        float xc = fminf(fmaxf(((v - WINDOW_A) * INV_AB - 0.5f) * 2.0f, -1.0f), 1.0f);

        // bin search: cum[j] <= (hx - (j+1)*MBH)*Sh/cH
        float ShocH = Sh * (1.0f / cH);
        float hx = fmaf(xc, 0.5f, 0.5f);
        float Rlo = (hx - (float)(lane + 1) * MBH) * ShocH;
        float Rhi = Rlo - 32.0f * MBH * ShocH;
        int cnt = (cum_lo <= Rlo) + (cum_hi <= Rhi);
        #pragma unroll
        for (int o = 16; o; o >>= 1) cnt += __shfl_xor_sync(FULL, cnt, o);
        int idx = min(cnt, 63);            // warp-uniform

        // gathers (idx uniform -> 1 shfl each, source select uniform)
        float vi = (idx & 32) ? cum_hi : cum_lo;
        float cumIdx = __shfl_sync(FULL, vi, idx & 31);
        int p = idx - 1;
        float v0 = (p & 32) ? cum_hi : cum_lo;
        float c0 = __shfl_sync(FULL, v0, p & 31);
        if (idx == 0) c0 = 0.0f;
        float uws = (idx & 32) ? uw1 : uw0;
        float ew_g = __expf(__shfl_sync(FULL, uws, idx & 31));

        idxr[r] = idx;
        c0r[r]  = c0;
        ehr[r]  = cumIdx - c0;             // exp(uh[idx])
        ewr[r]  = ew_g;
        swr_[r] = Sw;
        ishr[r] = __fdividef(1.0f, Sh);
    }

    // ---- parallel tail: group g = lanes 8g..8g+7 handles cut cb+g ----
    const int g = lane >> 3;
    const int s = lane & 7;
    long long cutl = cb + g;
    bool active = (cutl < n);
    int cut = active ? (int)cutl : (n - 1);

    int   idx   = sel4i(idxr, g);
    float c0    = sel4f(c0r, g);
    float eh_g  = sel4f(ehr, g);
    float ew_g  = sel4f(ewr, g);
    float Swl   = sel4f(swr_, g);
    float invSh = sel4f(ishr, g);

    // x per group (broadcast from prologue lanes)
    float v  = __shfl_sync(FULL, val_l, g);
    float x  = ((v - WINDOW_A) * INV_AB - 0.5f) * 2.0f;
    bool inside = (x >= -1.0f) && (x <= 1.0f);
    float xc = fminf(fmaxf(x, -1.0f), 1.0f);

    // derivatives: only 2 scattered loads per cut (ud region never streamed)
    const float* ds = delta_spline + (long long)cut * NSPL;
    int gene = __shfl_sync(FULL, gene_l, g);
    const float* sw = spline_weight + (long long)gene * NSPL;
    int i0 = max(idx - 1, 0);
    int i1 = min(idx, 62);
    float u0 = ds[2 * KB + i0] + sw[2 * KB + i0];
    float u1 = ds[2 * KB + i1] + sw[2 * KB + i1];
    if (idx == 0)  u0 = DEFAULT_INIT;
    if (idx == 63) u1 = DEFAULT_INIT;
    float d0 = MDER + softplus_f(u0);
    float d1 = MDER + softplus_f(u1);

    // spline quantities at idx
    float h_sm = fmaf(cH * invSh, eh_g, MBH);
    float w_sm = fmaf(cW, __fdividef(ew_g, Swl), MBW);
    float in_h = 2.0f * h_sm;
    float dlt  = __fdividef(h_sm, w_sm);
    float in_ch = fmaf(2.0f, fmaf(cH * invSh, c0, (float)idx * MBH), -1.0f);

    // rational-quadratic inverse, logabsdet only
    float dy = xc - in_ch;
    float sc = d0 + d1 - 2.0f * dlt;
    float a  = dy * sc + in_h * (dlt - d0);
    float b  = in_h * d0 - dy * sc;
    float c  = -dlt * dy;
    float disc = b * b - 4.0f * a * c;
    float root = __fdividef(2.0f * c, -b - sqrtf(fmaxf(disc, 0.0f)));
    float tom  = root * (1.0f - root);
    float denom = dlt + sc * tom;
    float omr  = 1.0f - root;
    float deriv_num = dlt * dlt * (d1 * root * root + 2.0f * dlt * tom + d0 * omr * omr);
    float logabsdet = -(__logf(deriv_num) - 2.0f * __logf(denom));

    float res = OUT_CONST + (inside ? logabsdet : 0.0f);
    if (s == 0 && active) out[cut] = res;        // 4 consecutive floats / warp
}

extern "C" void kernel_launch(void* const* d_in, const int* in_sizes, int n_in,
                              void* d_out, int out_size) {
    const float* value         = (const float*)d_in[0];
    const float* delta_spline  = (const float*)d_in[1];
    const int*   genes_oi      = (const int*)d_in[2];
    const int*   local_gene_ix = (const int*)d_in[3];
    const float* spline_weight = (const float*)d_in[4];
    float* out = (float*)d_out;
    int n = in_sizes[0];                      // N_CUTS
    int blocks = (n + 31) / 32;               // 32 cuts per 256-thread block
    rqs_logdet4h_kernel<<<blocks, 256>>>(value, delta_spline, genes_oi,
                                         local_gene_ix, spline_weight, out, n);
}

// round 12
// speedup vs baseline: 1.3426x; 1.3426x over previous
#include <cuda_runtime.h>
#include <cuda_bf16.h>

// Problem constants
#define NSPL 191               // 3*64 - 1 spline dims
#define KB   64                // bins
#define ROWP 136               // smem row stride (8 mod 32 -> conflict-free reads)

__device__ __forceinline__ float softplus_f(float x) {
    return fmaxf(x, 0.0f) + __logf(1.0f + __expf(-fabsf(x)));
}

// 8-way register select by uniform index k (0..7)
__device__ __forceinline__ float sel8(const float a[8], int k) {
    float x01 = (k & 1) ? a[1] : a[0];
    float x23 = (k & 1) ? a[3] : a[2];
    float x45 = (k & 1) ? a[5] : a[4];
    float x67 = (k & 1) ? a[7] : a[6];
    float y0  = (k & 2) ? x23 : x01;
    float y1  = (k & 2) ? x67 : x45;
    return (k & 4) ? y1 : y0;
}

// 4 cuts per warp, warp-private smem staging:
//  stage: warp-wide contiguous loads of each cut's fused (ds+sw) row -> smem
//  compute: R8's parallel width-8 layout; smem reads conflict-free.
__global__ __launch_bounds__(256)
void rqs_logdet4w_kernel(const float* __restrict__ value,
                         const float* __restrict__ delta_spline,
                         const int*   __restrict__ genes_oi,
                         const int*   __restrict__ local_gene_ix,
                         const float* __restrict__ spline_weight,
                         float*       __restrict__ out,
                         int n)
{
    const unsigned FULL = 0xffffffffu;
    const float WINDOW_A      = -10000.0f;
    const float INV_AB        = 1.0f / 20000.0f;
    const float MBW           = 0.001f;
    const float MBH           = 0.001f;
    const float MDER          = 0.001f;
    const float DEFAULT_INIT  = 0.53974366f;                 // log(exp(0.999)-1)
    const float OUT_CONST     = -0.69314718f - 9.90348755f;  // LOG_HALF - LOG_AB
    const float cH            = 1.0f - MBH * KB;             // 0.936
    const float cW            = 1.0f - MBW * KB;

    __shared__ __align__(16) float smem[8 * 4 * ROWP];   // 8 warps x 4 rows x 136

    const int lane = threadIdx.x & 31;
    int warp = (int)((blockIdx.x * (unsigned)blockDim.x + threadIdx.x) >> 5);
    long long cb = (long long)warp * 4;
    if (cb >= n) return;                         // warp-uniform exit
    float* su = smem + (threadIdx.x >> 5) * (4 * ROWP);

    // ---- prologue: lanes 0..3 fetch per-cut gene, broadcast via shfl ----
    int gene_l = 0;
    {
        long long ccl = cb + lane;
        int cc = (ccl < n) ? (int)ccl : (n - 1);
        if (lane < 4) gene_l = genes_oi[local_gene_ix[cc]];
    }

    // ---- stage: 4 rows x 128 cols, warp-wide contiguous (1 row per LDG) ----
    #pragma unroll
    for (int r = 0; r < 4; ++r) {
        long long ccl = cb + r;
        int cc = (ccl < n) ? (int)ccl : (n - 1);
        const float* ds = delta_spline + (long long)cc * NSPL;
        const float* sw = spline_weight
                        + (long long)__shfl_sync(FULL, gene_l, r) * NSPL;
        #pragma unroll
        for (int j = 0; j < 4; ++j) {
            int col = 32 * j + lane;
            su[r * ROWP + col] = ds[col] + sw[col];
        }
    }
    __syncwarp();

    // ---- compute: group g = lanes 8g..8g+7 handles cut cb+g ----
    const int g = lane >> 3;
    const int s = lane & 7;
    long long cutl = cb + g;
    bool active = (cutl < n);
    int cut = active ? (int)cutl : (n - 1);

    // strided ownership: lane s owns bins {8k+s}; conflict-free LDS
    float uwv[8], ehv[8];
    #pragma unroll
    for (int k = 0; k < 8; ++k) {
        int j = 8 * k + s;
        uwv[k] = su[g * ROWP + j];
        ehv[k] = __expf(su[g * ROWP + KB + j]);
    }

    // widths total
    float Swl = 0.0f;
    #pragma unroll
    for (int k = 0; k < 8; ++k) Swl += __expf(uwv[k]);
    #pragma unroll
    for (int o = 4; o; o >>= 1) Swl += __shfl_xor_sync(FULL, Swl, o, 8);

    // heights: 8 rounds of width-8 inclusive scan with carry
    float cum[8];
    float carry = 0.0f;
    #pragma unroll
    for (int k = 0; k < 8; ++k) {
        float isc = ehv[k];
        #pragma unroll
        for (int o = 1; o < 8; o <<= 1) {
            float u = __shfl_up_sync(FULL, isc, o, 8);
            if (s >= o) isc += u;
        }
        cum[k] = carry + isc;
        carry = __shfl_sync(FULL, cum[k], 7, 8);
    }
    float Sh = carry;

    // ---- x ----
    float v  = value[cut];
    float x  = ((v - WINDOW_A) * INV_AB - 0.5f) * 2.0f;
    bool inside = (x >= -1.0f) && (x <= 1.0f);
    float xc = fminf(fmaxf(x, -1.0f), 1.0f);

    // ---- bin search ----
    float invSh = __fdividef(1.0f, Sh);
    float ShocH = Sh * (1.0f / cH);
    float step8 = 8.0f * MBH * ShocH;
    float R = (fmaf(xc, 0.5f, 0.5f) - (float)(s + 1) * MBH) * ShocH;
    int cnt = 0;
    #pragma unroll
    for (int k = 0; k < 8; ++k) {
        cnt += (cum[k] <= R);
        R -= step8;
    }
    #pragma unroll
    for (int o = 4; o; o >>= 1) cnt += __shfl_xor_sync(FULL, cnt, o, 8);
    int idx = min(cnt, 63);                        // group-uniform

    // ---- register gathers at idx and idx-1 ----
    int k1 = idx >> 3, s1 = idx & 7;
    float cumIdx = __shfl_sync(FULL, sel8(cum, k1), s1, 8);
    int p  = idx - 1;
    int k0 = (p >= 0) ? (p >> 3) : 0;
    int s0 = p & 7;
    float c0 = __shfl_sync(FULL, sel8(cum, k0), s0, 8);
    if (idx == 0) c0 = 0.0f;
    float eh_g = cumIdx - c0;                      // exp(uh[idx])
    float ew_g = __expf(__shfl_sync(FULL, sel8(uwv, k1), s1, 8));

    // ---- derivatives: only 2 scattered loads (ud region never streamed) ----
    const float* ds = delta_spline + (long long)cut * NSPL;
    const float* sw = spline_weight
                    + (long long)__shfl_sync(FULL, gene_l, g) * NSPL;
    int i0 = max(idx - 1, 0);
    int i1 = min(idx, 62);
    float u0 = ds[2 * KB + i0] + sw[2 * KB + i0];
    float u1 = ds[2 * KB + i1] + sw[2 * KB + i1];
    if (idx == 0)  u0 = DEFAULT_INIT;
    if (idx == 63) u1 = DEFAULT_INIT;
    float d0 = MDER + softplus_f(u0);
    float d1 = MDER + softplus_f(u1);

    // ---- spline quantities at idx ----
    float h_sm = fmaf(cH * invSh, eh_g, MBH);
    float w_sm = fmaf(cW, __fdividef(ew_g, Swl), MBW);
    float in_h = 2.0f * h_sm;
    float dlt  = __fdividef(h_sm, w_sm);
    float in_ch = fmaf(2.0f, fmaf(cH * invSh, c0, (float)idx * MBH), -1.0f);

    // ---- rational-quadratic inverse, logabsdet only ----
    float dy = xc - in_ch;
    float sc = d0 + d1 - 2.0f * dlt;
    float a  = dy * sc + in_h * (dlt - d0);
    float b  = in_h * d0 - dy * sc;
    float c  = -dlt * dy;
    float disc = b * b - 4.0f * a * c;
    float root = __fdividef(2.0f * c, -b - sqrtf(fmaxf(disc, 0.0f)));
    float tom  = root * (1.0f - root);
    float denom = dlt + sc * tom;
    float omr  = 1.0f - root;
    float deriv_num = dlt * dlt * (d1 * root * root + 2.0f * dlt * tom + d0 * omr * omr);
    float logabsdet = -(__logf(deriv_num) - 2.0f * __logf(denom));

    float res = OUT_CONST + (inside ? logabsdet : 0.0f);
    if (s == 0 && active) out[cut] = res;          // 4 consecutive floats / warp
}

extern "C" void kernel_launch(void* const* d_in, const int* in_sizes, int n_in,
                              void* d_out, int out_size) {
    const float* value         = (const float*)d_in[0];
    const float* delta_spline  = (const float*)d_in[1];
    const int*   genes_oi      = (const int*)d_in[2];
    const int*   local_gene_ix = (const int*)d_in[3];
    const float* spline_weight = (const float*)d_in[4];
    float* out = (float*)d_out;
    int n = in_sizes[0];                      // N_CUTS
    int blocks = (n + 31) / 32;               // 32 cuts per 256-thread block
    rqs_logdet4w_kernel<<<blocks, 256>>>(value, delta_spline, genes_oi,
                                         local_gene_ix, spline_weight, out, n);
}